// round 1
// baseline (speedup 1.0000x reference)
#include <cuda_runtime.h>
#include <math.h>

#define N_RAYS    65536
#define N_SAMPLES 192
#define SPL       6                 // samples per lane (192 / 32)
#define WARPS_PER_BLOCK 8
#define THREADS   (WARPS_PER_BLOCK * 32)

// Output layout (flattened tuple, reference order):
//   rgb_map  : [0,            3N)
//   depth    : [3N,           4N)
//   acc      : [4N,           5N)
//   weights  : [5N,           5N + N*S)
//   disp     : [5N + N*S,     6N + N*S)
//   trans    : [6N + N*S,     6N + 2*N*S)
//   alpha    : [6N + 2*N*S,   6N + 3*N*S)

__global__ __launch_bounds__(THREADS)
void nerf_render_kernel(const float* __restrict__ rgb,
                        const float* __restrict__ sigma,
                        const float* __restrict__ z_vals,
                        const float* __restrict__ rays_d,
                        float* __restrict__ out)
{
    const int warp_id = threadIdx.x >> 5;
    const int lane    = threadIdx.x & 31;
    const int ray     = blockIdx.x * WARPS_PER_BLOCK + warp_id;
    if (ray >= N_RAYS) return;

    // ---- ray direction norm (same address across lanes -> broadcast) ----
    const float dx = rays_d[ray * 3 + 0];
    const float dy = rays_d[ray * 3 + 1];
    const float dz = rays_d[ray * 3 + 2];
    const float norm = sqrtf(dx * dx + dy * dy + dz * dz);

    const int base = ray * N_SAMPLES + lane * SPL;   // first sample owned by this lane

    // ---- load z (need one extra for dists); lane 31's extra is unused (dist=1e10) ----
    float z[SPL + 1];
#pragma unroll
    for (int i = 0; i < SPL; ++i) z[i] = z_vals[base + i];
    z[SPL] = (lane == 31) ? 0.0f : z_vals[base + SPL];

    float sg[SPL];
#pragma unroll
    for (int i = 0; i < SPL; ++i) sg[i] = sigma[base + i];

    // ---- alpha / (1 - alpha) per sample ----
    float alpha_v[SPL], om[SPL];
#pragma unroll
    for (int i = 0; i < SPL; ++i) {
        const int j = lane * SPL + i;                 // sample index within ray
        float dist = (j == N_SAMPLES - 1) ? 1e10f : (z[i + 1] - z[i]);
        dist *= norm;
        const float s = fmaxf(sg[i], 0.0f);
        const float e = __expf(-s * dist);            // = 1 - alpha
        om[i]      = e;
        alpha_v[i] = 1.0f - e;
    }

    // ---- within-lane exclusive prefix product of om ----
    float tl[SPL];                                    // local (exclusive) prefix
    float lp = 1.0f;
#pragma unroll
    for (int i = 0; i < SPL; ++i) { tl[i] = lp; lp *= om[i]; }

    // ---- warp inclusive scan (product) of lane totals, then exclusive shift ----
    float incl = lp;
#pragma unroll
    for (int off = 1; off < 32; off <<= 1) {
        const float v = __shfl_up_sync(0xffffffffu, incl, off);
        if (lane >= off) incl *= v;
    }
    float excl = __shfl_up_sync(0xffffffffu, incl, 1);
    if (lane == 0) excl = 1.0f;

    // ---- per-sample outputs + per-ray partial reductions ----
    float* __restrict__ out_rgbm = out;
    float* __restrict__ out_dep  = out + 3 * N_RAYS;
    float* __restrict__ out_acc  = out + 4 * N_RAYS;
    float* __restrict__ out_w    = out + 5 * N_RAYS;
    float* __restrict__ out_disp = out + 5 * N_RAYS + (size_t)N_RAYS * N_SAMPLES;
    float* __restrict__ out_t    = out + 6 * N_RAYS + (size_t)N_RAYS * N_SAMPLES;
    float* __restrict__ out_a    = out + 6 * N_RAYS + 2 * (size_t)N_RAYS * N_SAMPLES;

    float sw = 0.0f, swz = 0.0f, sr = 0.0f, sgc = 0.0f, sb = 0.0f;
#pragma unroll
    for (int i = 0; i < SPL; ++i) {
        const float t = excl * tl[i];                 // transmittance T_j
        const float w = alpha_v[i] * t;               // weight
        sw  += w;
        swz  = fmaf(w, z[i], swz);
        const int rb = (base + i) * 3;
        sr   = fmaf(w, rgb[rb + 0], sr);
        sgc  = fmaf(w, rgb[rb + 1], sgc);
        sb   = fmaf(w, rgb[rb + 2], sb);
        out_w[base + i] = w;
        out_t[base + i] = t;
        out_a[base + i] = alpha_v[i];
    }

    // ---- warp butterfly reductions ----
#pragma unroll
    for (int off = 16; off >= 1; off >>= 1) {
        sw  += __shfl_xor_sync(0xffffffffu, sw,  off);
        swz += __shfl_xor_sync(0xffffffffu, swz, off);
        sr  += __shfl_xor_sync(0xffffffffu, sr,  off);
        sgc += __shfl_xor_sync(0xffffffffu, sgc, off);
        sb  += __shfl_xor_sync(0xffffffffu, sb,  off);
    }

    if (lane == 0) {
        out_rgbm[ray * 3 + 0] = sr;
        out_rgbm[ray * 3 + 1] = sgc;
        out_rgbm[ray * 3 + 2] = sb;
        out_dep[ray] = swz;
        out_acc[ray] = sw;
        out_disp[ray] = 1.0f / fmaxf(1e-10f, swz / sw);
    }
}

extern "C" void kernel_launch(void* const* d_in, const int* in_sizes, int n_in,
                              void* d_out, int out_size)
{
    const float* rgb    = (const float*)d_in[0];
    const float* sigma  = (const float*)d_in[1];
    const float* z_vals = (const float*)d_in[2];
    const float* rays_d = (const float*)d_in[3];
    float* out = (float*)d_out;

    const int blocks = N_RAYS / WARPS_PER_BLOCK;   // 8192
    nerf_render_kernel<<<blocks, THREADS>>>(rgb, sigma, z_vals, rays_d, out);
}

// round 2
// speedup vs baseline: 2.6262x; 2.6262x over previous
#include <cuda_runtime.h>
#include <math.h>

#define N_RAYS    65536
#define N_SAMPLES 192
#define CHUNKS    6                   // 192 / 32
#define WARPS_PER_BLOCK 8
#define THREADS   (WARPS_PER_BLOCK * 32)
#define FULL      0xffffffffu

// Output layout (flattened tuple, reference order):
//   rgb_map | depth | acc | weights | disp | trans | alpha

__global__ __launch_bounds__(THREADS)
void nerf_render_kernel(const float* __restrict__ rgb,
                        const float* __restrict__ sigma,
                        const float* __restrict__ z_vals,
                        const float* __restrict__ rays_d,
                        float* __restrict__ out)
{
    __shared__ __align__(16) float srgb[WARPS_PER_BLOCK][N_SAMPLES * 3]; // 576 floats/warp

    const int warp = threadIdx.x >> 5;
    const int lane = threadIdx.x & 31;
    const int ray  = blockIdx.x * WARPS_PER_BLOCK + warp;

    // ---- ray direction norm (broadcast loads) ----
    const float dx = rays_d[ray * 3 + 0];
    const float dy = rays_d[ray * 3 + 1];
    const float dz = rays_d[ray * 3 + 2];
    const float norm = sqrtf(dx * dx + dy * dy + dz * dz);

    const int rowbase = ray * N_SAMPLES;              // sample base for this ray

    // ---- coalesced loads: lane owns samples c*32 + lane ----
    float z[CHUNKS], sg[CHUNKS];
#pragma unroll
    for (int c = 0; c < CHUNKS; ++c) {
        const int idx = rowbase + c * 32 + lane;
        z[c]  = z_vals[idx];
        sg[c] = sigma[idx];
    }

    // ---- stage rgb row (576 floats) into smem via vectorized coalesced loads ----
    {
        const float* __restrict__ rowp = rgb + (size_t)ray * (N_SAMPLES * 3);
        const float4* __restrict__ row4 = (const float4*)rowp;      // 144 float4
#pragma unroll
        for (int k = 0; k < 4; ++k) {                                // 128 float4
            const int e = lane + 32 * k;
            *(float4*)&srgb[warp][e * 4] = row4[e];
        }
        // remaining 64 floats as float2
        *(float2*)&srgb[warp][512 + lane * 2] = ((const float2*)(rowp + 512))[lane];
    }
    __syncwarp();

    float* __restrict__ out_rgbm = out;
    float* __restrict__ out_dep  = out + 3 * N_RAYS;
    float* __restrict__ out_acc  = out + 4 * N_RAYS;
    float* __restrict__ out_w    = out + 5 * N_RAYS;
    float* __restrict__ out_disp = out + 5 * N_RAYS + (size_t)N_RAYS * N_SAMPLES;
    float* __restrict__ out_t    = out + 6 * N_RAYS + (size_t)N_RAYS * N_SAMPLES;
    float* __restrict__ out_a    = out + 6 * N_RAYS + 2 * (size_t)N_RAYS * N_SAMPLES;

    float carry = 1.0f;                                // transmittance into chunk c
    float sw = 0.0f, swz = 0.0f, sr = 0.0f, sgc = 0.0f, sb = 0.0f;

#pragma unroll
    for (int c = 0; c < CHUNKS; ++c) {
        // ---- dist: z[s+1] - z[s]; neighbor via shuffle, chunk boundary from next chunk ----
        float znext = __shfl_down_sync(FULL, z[c], 1);
        if (c < CHUNKS - 1) {
            const float zn0 = __shfl_sync(FULL, z[c + 1], 0);
            if (lane == 31) znext = zn0;
        }
        float dist;
        if (c == CHUNKS - 1)
            dist = (lane == 31) ? 1e10f : (znext - z[c]);
        else
            dist = znext - z[c];
        dist *= norm;

        const float s  = fmaxf(sg[c], 0.0f);
        const float om = __expf(-s * dist);            // 1 - alpha
        const float alpha = 1.0f - om;

        // ---- warp inclusive product scan of om within chunk ----
        float incl = om;
#pragma unroll
        for (int off = 1; off < 32; off <<= 1) {
            const float v = __shfl_up_sync(FULL, incl, off);
            if (lane >= off) incl *= v;
        }
        float excl = __shfl_up_sync(FULL, incl, 1);
        if (lane == 0) excl = 1.0f;

        const float t = carry * excl;                  // transmittance T_s
        carry *= __shfl_sync(FULL, incl, 31);          // carry product into next chunk
        const float w = alpha * t;

        // ---- coalesced per-sample stores ----
        const int idx = rowbase + c * 32 + lane;
        out_w[idx] = w;
        out_t[idx] = t;
        out_a[idx] = alpha;

        // ---- per-ray partial sums (rgb from smem, stride-3 = conflict-free) ----
        sw  += w;
        swz  = fmaf(w, z[c], swz);
        const int p = (c * 32 + lane) * 3;
        sr   = fmaf(w, srgb[warp][p + 0], sr);
        sgc  = fmaf(w, srgb[warp][p + 1], sgc);
        sb   = fmaf(w, srgb[warp][p + 2], sb);
    }

    // ---- warp butterfly reductions ----
#pragma unroll
    for (int off = 16; off >= 1; off >>= 1) {
        sw  += __shfl_xor_sync(FULL, sw,  off);
        swz += __shfl_xor_sync(FULL, swz, off);
        sr  += __shfl_xor_sync(FULL, sr,  off);
        sgc += __shfl_xor_sync(FULL, sgc, off);
        sb  += __shfl_xor_sync(FULL, sb,  off);
    }

    if (lane == 0) {
        out_rgbm[ray * 3 + 0] = sr;
        out_rgbm[ray * 3 + 1] = sgc;
        out_rgbm[ray * 3 + 2] = sb;
        out_dep[ray]  = swz;
        out_acc[ray]  = sw;
        out_disp[ray] = 1.0f / fmaxf(1e-10f, swz / sw);
    }
}

extern "C" void kernel_launch(void* const* d_in, const int* in_sizes, int n_in,
                              void* d_out, int out_size)
{
    const float* rgb    = (const float*)d_in[0];
    const float* sigma  = (const float*)d_in[1];
    const float* z_vals = (const float*)d_in[2];
    const float* rays_d = (const float*)d_in[3];
    float* out = (float*)d_out;

    nerf_render_kernel<<<N_RAYS / WARPS_PER_BLOCK, THREADS>>>(rgb, sigma, z_vals, rays_d, out);
}

// round 3
// speedup vs baseline: 3.1136x; 1.1856x over previous
#include <cuda_runtime.h>
#include <math.h>

#define N_RAYS    65536
#define N_SAMPLES 192
#define CHUNKS    6                   // 192 / 32
#define WARPS_PER_BLOCK 8
#define THREADS   (WARPS_PER_BLOCK * 32)
#define FULL      0xffffffffu

// Output layout (flattened tuple, reference order):
//   rgb_map | depth | acc | weights | disp | trans | alpha

__global__ __launch_bounds__(THREADS)
void nerf_render_kernel(const float* __restrict__ rgb,
                        const float* __restrict__ sigma,
                        const float* __restrict__ z_vals,
                        const float* __restrict__ rays_d,
                        float* __restrict__ out)
{
    __shared__ __align__(16) float srgb[WARPS_PER_BLOCK][N_SAMPLES * 3]; // 576 floats/warp

    const int warp = threadIdx.x >> 5;
    const int lane = threadIdx.x & 31;
    const int ray  = blockIdx.x * WARPS_PER_BLOCK + warp;

    const int rowbase = ray * N_SAMPLES;

    // ---- front-batched coalesced streaming loads (max MLP) ----
    float z[CHUNKS], sg[CHUNKS];
#pragma unroll
    for (int c = 0; c < CHUNKS; ++c) {
        const int idx = rowbase + c * 32 + lane;
        z[c]  = __ldcs(&z_vals[idx]);
        sg[c] = __ldcs(&sigma[idx]);
    }

    // rgb row (576 floats) -> smem, vectorized + streaming
    {
        const float* __restrict__ rowp = rgb + (size_t)ray * (N_SAMPLES * 3);
        const float4* __restrict__ row4 = (const float4*)rowp;
#pragma unroll
        for (int k = 0; k < 4; ++k) {
            const int e = lane + 32 * k;
            *(float4*)&srgb[warp][e * 4] = __ldcs(&row4[e]);
        }
        *(float2*)&srgb[warp][512 + lane * 2] = __ldcs(((const float2*)(rowp + 512)) + lane);
    }

    // rays_d (broadcast, tiny, cached)
    const float dx = rays_d[ray * 3 + 0];
    const float dy = rays_d[ray * 3 + 1];
    const float dz = rays_d[ray * 3 + 2];
    const float norm = sqrtf(dx * dx + dy * dy + dz * dz);

    // ---- alpha / (1-alpha) for all chunks ----
    float alpha_v[CHUNKS], om[CHUNKS];
#pragma unroll
    for (int c = 0; c < CHUNKS; ++c) {
        float znext = __shfl_down_sync(FULL, z[c], 1);
        if (c < CHUNKS - 1) {
            const float zn0 = __shfl_sync(FULL, z[c + 1], 0);
            if (lane == 31) znext = zn0;
        }
        float dist;
        if (c == CHUNKS - 1)
            dist = (lane == 31) ? 1e10f : (znext - z[c]);
        else
            dist = znext - z[c];
        dist *= norm;

        const float s = fmaxf(sg[c], 0.0f);
        om[c]      = __expf(-s * dist);
        alpha_v[c] = 1.0f - om[c];
    }

    // ---- 6 INDEPENDENT warp product-scans (ILP across chunks) ----
    float incl[CHUNKS];
#pragma unroll
    for (int c = 0; c < CHUNKS; ++c) incl[c] = om[c];
#pragma unroll
    for (int off = 1; off < 32; off <<= 1) {
#pragma unroll
        for (int c = 0; c < CHUNKS; ++c) {
            const float v = __shfl_up_sync(FULL, incl[c], off);
            if (lane >= off) incl[c] *= v;
        }
    }

    // exclusive within chunk + carry across chunks (short sequential chain)
    float texcl[CHUNKS];
    float carry = 1.0f;
#pragma unroll
    for (int c = 0; c < CHUNKS; ++c) {
        float e = __shfl_up_sync(FULL, incl[c], 1);
        if (lane == 0) e = 1.0f;
        texcl[c] = carry * e;                              // T_s
        carry *= __shfl_sync(FULL, incl[c], 31);
    }

    float* __restrict__ out_rgbm = out;
    float* __restrict__ out_dep  = out + 3 * N_RAYS;
    float* __restrict__ out_acc  = out + 4 * N_RAYS;
    float* __restrict__ out_w    = out + 5 * N_RAYS;
    float* __restrict__ out_disp = out + 5 * N_RAYS + (size_t)N_RAYS * N_SAMPLES;
    float* __restrict__ out_t    = out + 6 * N_RAYS + (size_t)N_RAYS * N_SAMPLES;
    float* __restrict__ out_a    = out + 6 * N_RAYS + 2 * (size_t)N_RAYS * N_SAMPLES;

    // ---- batched streaming stores ----
    float w[CHUNKS];
#pragma unroll
    for (int c = 0; c < CHUNKS; ++c) w[c] = alpha_v[c] * texcl[c];

    __syncwarp();   // srgb visible (also orders the earlier smem writes)

#pragma unroll
    for (int c = 0; c < CHUNKS; ++c) {
        const int idx = rowbase + c * 32 + lane;
        __stcs(&out_w[idx], w[c]);
        __stcs(&out_t[idx], texcl[c]);
        __stcs(&out_a[idx], alpha_v[c]);
    }

    // ---- per-ray reductions (rgb from smem, stride-3 = conflict-free) ----
    float sw = 0.0f, swz = 0.0f, sr = 0.0f, sgc = 0.0f, sb = 0.0f;
#pragma unroll
    for (int c = 0; c < CHUNKS; ++c) {
        sw  += w[c];
        swz  = fmaf(w[c], z[c], swz);
        const int p = (c * 32 + lane) * 3;
        sr   = fmaf(w[c], srgb[warp][p + 0], sr);
        sgc  = fmaf(w[c], srgb[warp][p + 1], sgc);
        sb   = fmaf(w[c], srgb[warp][p + 2], sb);
    }

#pragma unroll
    for (int off = 16; off >= 1; off >>= 1) {
        sw  += __shfl_xor_sync(FULL, sw,  off);
        swz += __shfl_xor_sync(FULL, swz, off);
        sr  += __shfl_xor_sync(FULL, sr,  off);
        sgc += __shfl_xor_sync(FULL, sgc, off);
        sb  += __shfl_xor_sync(FULL, sb,  off);
    }

    if (lane == 0) {
        out_rgbm[ray * 3 + 0] = sr;
        out_rgbm[ray * 3 + 1] = sgc;
        out_rgbm[ray * 3 + 2] = sb;
        out_dep[ray]  = swz;
        out_acc[ray]  = sw;
        out_disp[ray] = 1.0f / fmaxf(1e-10f, swz / sw);
    }
}

extern "C" void kernel_launch(void* const* d_in, const int* in_sizes, int n_in,
                              void* d_out, int out_size)
{
    const float* rgb    = (const float*)d_in[0];
    const float* sigma  = (const float*)d_in[1];
    const float* z_vals = (const float*)d_in[2];
    const float* rays_d = (const float*)d_in[3];
    float* out = (float*)d_out;

    nerf_render_kernel<<<N_RAYS / WARPS_PER_BLOCK, THREADS>>>(rgb, sigma, z_vals, rays_d, out);
}